// round 6
// baseline (speedup 1.0000x reference)
#include <cuda_runtime.h>
#include <cuda_bf16.h>

// Thread-per-row hierarchical softmax, 2-sync single-buffer design.
// Fused output layout (flat): [ leaf_path_probs (N*65) | node_probs (N*76) ]

#define NT     128
#define ROWS   128
#define STRIDE 68    // padded row stride in shared (17 float4, %4==0 for aligned LDS.128)

__global__ __launch_bounds__(NT, 5)
void molemap_kernel(const float* __restrict__ x,
                    float* __restrict__ out_path,
                    float* __restrict__ out_node)
{
    // buf holds input rows, then (in place) leaf probs, padded to stride 68
    __shared__ __align__(16) float buf[ROWS * STRIDE];   // 34816 B
    __shared__ float sN[ROWS][12];   // per row: pl2[0..7], pt0, pt1   (node tail)
    __shared__ float sC[ROWS][8];    // per row: pl2[g] * pt[branch]   (path scale)
    __shared__ int   sg[68];         // leaf -> group

    const int tid = threadIdx.x;
    const long long row0 = (long long)blockIdx.x * ROWS;

    if (tid < 68)
        sg[tid] = (tid >= 7) + (tid >= 30) + (tid >= 48) + (tid >= 53) +
                  (tid >= 58) + (tid >= 59) + (tid >= 62);

    // ---- Phase A: coalesced vectorized load, scatter into padded rows ----
    {
        const float4* in4 = reinterpret_cast<const float4*>(x + row0 * 65);
        #pragma unroll
        for (int k = 0; k < 17; ++k) {
            int j = tid + k * NT;
            if (j < 2080) {
                float4 val = __ldcs(&in4[j]);
                int f = 4 * j;
                int r = f / 65, i = f - 65 * r;
                buf[r * STRIDE + i] = val.x; if (++i == 65) { i = 0; ++r; }
                buf[r * STRIDE + i] = val.y; if (++i == 65) { i = 0; ++r; }
                buf[r * STRIDE + i] = val.z; if (++i == 65) { i = 0; ++r; }
                buf[r * STRIDE + i] = val.w;
            }
        }
    }
    __syncthreads();

    // ---- Phase B: thread-per-row compute; buf row -> leaf probs in place ----
    {
        float4* rv4 = reinterpret_cast<float4*>(buf) + tid * (STRIDE / 4);
        float v[STRIDE];
        float4* vv = reinterpret_cast<float4*>(v);
        #pragma unroll
        for (int k = 0; k < 17; ++k) vv[k] = rv4[k];   // conflict-free LDS.128

        float m[8], grcp[8], mean[8];
#define GROUP_STATS(G, A, B, RSZ)                                       \
        {                                                               \
            float mm = v[A], s = 0.f;                                   \
            _Pragma("unroll")                                           \
            for (int i = A; i < B; ++i) { s += v[i]; mm = fmaxf(mm, v[i]); } \
            float e = 0.f;                                              \
            _Pragma("unroll")                                           \
            for (int i = A; i < B; ++i) { v[i] = __expf(v[i] - mm); e += v[i]; } \
            m[G] = mm; grcp[G] = 1.0f / e; mean[G] = s * (RSZ);         \
        }
        GROUP_STATS(0,  0,  7, 1.0f/7.0f)
        GROUP_STATS(1,  7, 30, 1.0f/23.0f)
        GROUP_STATS(2, 30, 48, 1.0f/18.0f)
        GROUP_STATS(3, 48, 53, 1.0f/5.0f)
        GROUP_STATS(4, 53, 58, 1.0f/5.0f)
        GROUP_STATS(5, 58, 59, 1.0f)
        GROUP_STATS(6, 59, 62, 1.0f/3.0f)
        GROUP_STATS(7, 62, 65, 1.0f/3.0f)
#undef GROUP_STATS

        // leaf probs in place
#define LEAF(G, A, B)                                       \
        _Pragma("unroll")                                   \
        for (int i = A; i < B; ++i) v[i] *= grcp[G];
        LEAF(0,  0,  7)  LEAF(1,  7, 30)  LEAF(2, 30, 48)  LEAF(3, 48, 53)
        LEAF(4, 53, 58)  LEAF(5, 58, 59)  LEAF(6, 59, 62)  LEAF(7, 62, 65)
#undef LEAF
        v[65] = 0.f; v[66] = 0.f; v[67] = 0.f;

        // level-2 softmaxes + top softmax
        float pl2[8], pt0, pt1;
        {
            float mx0 = fmaxf(fmaxf(mean[0], mean[1]), fmaxf(mean[2], mean[3]));
            float e0 = __expf(mean[0]-mx0), e1 = __expf(mean[1]-mx0);
            float e2 = __expf(mean[2]-mx0), e3 = __expf(mean[3]-mx0);
            float r0 = 1.0f / (e0 + e1 + e2 + e3);
            pl2[0] = e0*r0; pl2[1] = e1*r0; pl2[2] = e2*r0; pl2[3] = e3*r0;

            float mx1 = fmaxf(fmaxf(mean[4], mean[5]), fmaxf(mean[6], mean[7]));
            float f0 = __expf(mean[4]-mx1), f1 = __expf(mean[5]-mx1);
            float f2 = __expf(mean[6]-mx1), f3 = __expf(mean[7]-mx1);
            float r1 = 1.0f / (f0 + f1 + f2 + f3);
            pl2[4] = f0*r1; pl2[5] = f1*r1; pl2[6] = f2*r1; pl2[7] = f3*r1;

            float m0 = (mean[0]*7.f + mean[1]*23.f + mean[2]*18.f + mean[3]*5.f) * (1.0f/53.0f);
            float m1 = (mean[4]*5.f + mean[5]*1.f + mean[6]*3.f + mean[7]*3.f) * (1.0f/12.0f);
            float mxt = fmaxf(m0, m1);
            float t0 = __expf(m0 - mxt), t1 = __expf(m1 - mxt);
            float rt = 1.0f / (t0 + t1);
            pt0 = t0 * rt; pt1 = t1 * rt;
        }

        #pragma unroll
        for (int k = 0; k < 17; ++k) rv4[k] = vv[k];   // leaf probs back, STS.128

        #pragma unroll
        for (int g = 0; g < 8; ++g) {
            sN[tid][g] = pl2[g];
            sC[tid][g] = pl2[g] * (g < 4 ? pt0 : pt1);
        }
        sN[tid][8] = pt0;
        sN[tid][9] = pt1;
    }
    __syncthreads();

    // ---- Phase C: stream node_probs (2432 float4, exact), read-only on smem ----
    {
        float4* on4 = reinterpret_cast<float4*>(out_node + row0 * 76);  // 304B rows: 16B aligned
        const float4* b4 = reinterpret_cast<const float4*>(buf);
        #pragma unroll
        for (int k = 0; k < 19; ++k) {
            int j = tid + k * NT;
            int r = j / 19, q = j - 19 * r;
            float4 o;
            if (q < 16) {
                o = b4[r * (STRIDE/4) + q];
            } else if (q == 16) {
                o.x = buf[r * STRIDE + 64];
                o.y = sN[r][0]; o.z = sN[r][1]; o.w = sN[r][2];
            } else if (q == 17) {
                o.x = sN[r][3]; o.y = sN[r][4]; o.z = sN[r][5]; o.w = sN[r][6];
            } else {
                o.x = sN[r][7]; o.y = sN[r][8]; o.z = sN[r][9]; o.w = 1.0f;
            }
            __stcs(&on4[j], o);
        }
    }

    // ---- Phase D: stream leaf_path_probs (2080 float4), read-only on smem ----
    {
        float4* op4 = reinterpret_cast<float4*>(out_path + row0 * 65);
        #pragma unroll
        for (int k = 0; k < 17; ++k) {
            int j = tid + k * NT;
            if (j < 2080) {
                int f = 4 * j;
                int r = f / 65, i = f - 65 * r;
                float4 o;
                o.x = buf[r * STRIDE + i] * sC[r][sg[i]]; if (++i == 65) { i = 0; ++r; }
                o.y = buf[r * STRIDE + i] * sC[r][sg[i]]; if (++i == 65) { i = 0; ++r; }
                o.z = buf[r * STRIDE + i] * sC[r][sg[i]]; if (++i == 65) { i = 0; ++r; }
                o.w = buf[r * STRIDE + i] * sC[r][sg[i]];
                __stcs(&op4[j], o);
            }
        }
    }
}

extern "C" void kernel_launch(void* const* d_in, const int* in_sizes, int n_in,
                              void* d_out, int out_size)
{
    const float* x = (const float*)d_in[0];
    const long long N = (long long)in_sizes[0] / 65;   // 524288
    float* out_path = (float*)d_out;
    float* out_node = out_path + N * 65;

    const int blocks = (int)(N / ROWS);                // 4096
    molemap_kernel<<<blocks, NT>>>(x, out_path, out_node);
}

// round 7
// speedup vs baseline: 1.3168x; 1.3168x over previous
#include <cuda_runtime.h>
#include <cuda_bf16.h>

// Thread-per-row hierarchical softmax (round-4 skeleton, occupancy-fixed).
// Fused output layout (flat): [ leaf_path_probs (N*65) | node_probs (N*76) ]

#define NT   128
#define ROWS 128

__global__ __launch_bounds__(NT, 5)
void molemap_kernel(const float* __restrict__ x,
                    float* __restrict__ out_path,
                    float* __restrict__ out_node)
{
    // One reused buffer: input rows -> path probs (stride 65) -> node rows (stride 76)
    __shared__ __align__(16) float buf[ROWS * 76];   // 38912 B
    __shared__ float sN[ROWS][10];    // per row: pl2[0..7], pt0, pt1
    __shared__ float sInv[ROWS][8];   // per row: 1/(pl2[g]*pt[branch])

    const int tid = threadIdx.x;
    const long long row0 = (long long)blockIdx.x * ROWS;

    // ---- Phase A: coalesced vectorized load, 128*65 = 2080 float4 ----
    {
        const float4* in4 = reinterpret_cast<const float4*>(x + row0 * 65);
        float4* b4 = reinterpret_cast<float4*>(buf);
        #pragma unroll
        for (int k = 0; k < 17; ++k) {
            int idx = tid + k * NT;
            if (idx < 2080) b4[idx] = __ldcs(&in4[idx]);
        }
    }
    __syncthreads();

    // ---- Phase B: thread-per-row compute; path probs written in place ----
    {
        float* rx = buf + tid * 65;   // stride 65 ≡ 1 (mod 32): conflict-free
        float v[65];
        #pragma unroll
        for (int i = 0; i < 65; ++i) v[i] = rx[i];

        float grcp[8], mean[8];
#define GROUP_STATS(G, A, B, RSZ)                                       \
        {                                                               \
            float mm = v[A], s = 0.f;                                   \
            _Pragma("unroll")                                           \
            for (int i = A; i < B; ++i) { s += v[i]; mm = fmaxf(mm, v[i]); } \
            float e = 0.f;                                              \
            _Pragma("unroll")                                           \
            for (int i = A; i < B; ++i) { v[i] = __expf(v[i] - mm); e += v[i]; } \
            grcp[G] = 1.0f / e; mean[G] = s * (RSZ);                    \
        }
        GROUP_STATS(0,  0,  7, 1.0f/7.0f)
        GROUP_STATS(1,  7, 30, 1.0f/23.0f)
        GROUP_STATS(2, 30, 48, 1.0f/18.0f)
        GROUP_STATS(3, 48, 53, 1.0f/5.0f)
        GROUP_STATS(4, 53, 58, 1.0f/5.0f)
        GROUP_STATS(5, 58, 59, 1.0f)
        GROUP_STATS(6, 59, 62, 1.0f/3.0f)
        GROUP_STATS(7, 62, 65, 1.0f/3.0f)
#undef GROUP_STATS

        // level-2 softmaxes + top softmax
        float pl2[8], pt0, pt1;
        {
            float mx0 = fmaxf(fmaxf(mean[0], mean[1]), fmaxf(mean[2], mean[3]));
            float e0 = __expf(mean[0]-mx0), e1 = __expf(mean[1]-mx0);
            float e2 = __expf(mean[2]-mx0), e3 = __expf(mean[3]-mx0);
            float r0 = 1.0f / (e0 + e1 + e2 + e3);
            pl2[0] = e0*r0; pl2[1] = e1*r0; pl2[2] = e2*r0; pl2[3] = e3*r0;

            float mx1 = fmaxf(fmaxf(mean[4], mean[5]), fmaxf(mean[6], mean[7]));
            float f0 = __expf(mean[4]-mx1), f1 = __expf(mean[5]-mx1);
            float f2 = __expf(mean[6]-mx1), f3 = __expf(mean[7]-mx1);
            float r1 = 1.0f / (f0 + f1 + f2 + f3);
            pl2[4] = f0*r1; pl2[5] = f1*r1; pl2[6] = f2*r1; pl2[7] = f3*r1;

            float m0 = (mean[0]*7.f + mean[1]*23.f + mean[2]*18.f + mean[3]*5.f) * (1.0f/53.0f);
            float m1 = (mean[4]*5.f + mean[5]*1.f + mean[6]*3.f + mean[7]*3.f) * (1.0f/12.0f);
            float mxt = fmaxf(m0, m1);
            float t0 = __expf(m0 - mxt), t1 = __expf(m1 - mxt);
            float rt = 1.0f / (t0 + t1);
            pt0 = t0 * rt; pt1 = t1 * rt;
        }

        // fused path scale per group, and its pl2*pt reciprocal for later leaf recovery
        float ks[8];
        #pragma unroll
        for (int g = 0; g < 8; ++g) {
            float br = (g < 4) ? pt0 : pt1;
            float pp = pl2[g] * br;
            ks[g] = grcp[g] * pp;
            sInv[tid][g] = 1.0f / pp;
            sN[tid][g] = pl2[g];
        }
        sN[tid][8] = pt0;
        sN[tid][9] = pt1;

        // path probs in place (own row only)
#define PATH_WRITE(G, A, B)                                   \
        _Pragma("unroll")                                     \
        for (int i = A; i < B; ++i) rx[i] = v[i] * ks[G];
        PATH_WRITE(0,  0,  7)  PATH_WRITE(1,  7, 30)
        PATH_WRITE(2, 30, 48)  PATH_WRITE(3, 48, 53)
        PATH_WRITE(4, 53, 58)  PATH_WRITE(5, 58, 59)
        PATH_WRITE(6, 59, 62)  PATH_WRITE(7, 62, 65)
#undef PATH_WRITE
    }   // v[] dead here
    __syncthreads();

    // ---- Phase C: stream path probs out, 2080 float4 (read-only on buf) ----
    {
        float4* op4 = reinterpret_cast<float4*>(out_path + row0 * 65);
        const float4* b4 = reinterpret_cast<const float4*>(buf);
        #pragma unroll
        for (int k = 0; k < 17; ++k) {
            int idx = tid + k * NT;
            if (idx < 2080) __stcs(&op4[idx], b4[idx]);
        }
    }

    // ---- Phase C2: recover leaf probs = path * 1/(pl2*pt) (read-only on buf) ----
    float v[65];
    {
        const float* rx = buf + tid * 65;
#define LEAF_RECOVER(G, A, B)                                 \
        {                                                     \
            float inv = sInv[tid][G];                         \
            _Pragma("unroll")                                 \
            for (int i = A; i < B; ++i) v[i] = rx[i] * inv;   \
        }
        LEAF_RECOVER(0,  0,  7)  LEAF_RECOVER(1,  7, 30)
        LEAF_RECOVER(2, 30, 48)  LEAF_RECOVER(3, 48, 53)
        LEAF_RECOVER(4, 53, 58)  LEAF_RECOVER(5, 58, 59)
        LEAF_RECOVER(6, 59, 62)  LEAF_RECOVER(7, 62, 65)
#undef LEAF_RECOVER
    }
    __syncthreads();   // all reads of path layout done before node-layout overwrite

    // ---- Phase D: write node rows [128][76] in place ----
    {
        float* rn = buf + tid * 76;
        #pragma unroll
        for (int i = 0; i < 65; ++i) rn[i] = v[i];
        #pragma unroll
        for (int g = 0; g < 8; ++g) rn[65 + g] = sN[tid][g];
        rn[73] = sN[tid][8];
        rn[74] = sN[tid][9];
        rn[75] = 1.0f;
    }
    __syncthreads();

    // ---- Phase E: stream node_probs out, 128*76 = 2432 float4 exact ----
    {
        float4* on4 = reinterpret_cast<float4*>(out_node + row0 * 76);
        const float4* b4 = reinterpret_cast<const float4*>(buf);
        #pragma unroll
        for (int k = 0; k < 19; ++k) {
            int idx = tid + k * NT;
            __stcs(&on4[idx], b4[idx]);
        }
    }
}

extern "C" void kernel_launch(void* const* d_in, const int* in_sizes, int n_in,
                              void* d_out, int out_size)
{
    const float* x = (const float*)d_in[0];
    const long long N = (long long)in_sizes[0] / 65;   // 524288
    float* out_path = (float*)d_out;
    float* out_node = out_path + N * 65;

    const int blocks = (int)(N / ROWS);                // 4096
    molemap_kernel<<<blocks, NT>>>(x, out_path, out_node);
}

// round 8
// speedup vs baseline: 1.4057x; 1.0675x over previous
#include <cuda_runtime.h>
#include <cuda_bf16.h>

// Thread-per-row hierarchical softmax. 5 blocks/SM: smem = one 38912B buffer,
// regs capped at 102 via launch_bounds; per-row scalars live in registers.
// Fused output layout (flat): [ leaf_path_probs (N*65) | node_probs (N*76) ]

#define NT   128
#define ROWS 128

__global__ __launch_bounds__(NT, 5)
void molemap_kernel(const float* __restrict__ x,
                    float* __restrict__ out_path,
                    float* __restrict__ out_node)
{
    // ONLY smem: reused buffer. input rows -> path probs (stride 65) -> node rows (stride 76)
    __shared__ __align__(16) float buf[ROWS * 76];   // 38912 B

    const int tid = threadIdx.x;
    const long long row0 = (long long)blockIdx.x * ROWS;

    // ---- Phase A: coalesced vectorized load, 128*65 = 2080 float4 ----
    {
        const float4* in4 = reinterpret_cast<const float4*>(x + row0 * 65);
        float4* b4 = reinterpret_cast<float4*>(buf);
        #pragma unroll
        for (int k = 0; k < 17; ++k) {
            int idx = tid + k * NT;
            if (idx < 2080) b4[idx] = __ldcs(&in4[idx]);
        }
    }
    __syncthreads();

    // Per-row scalars kept in REGISTERS across streaming phases (tid-private).
    float pl2[8], pt0, pt1, inv[8];

    // ---- Phase B: thread-per-row compute; path probs written in place ----
    {
        float* rx = buf + tid * 65;   // stride 65 ≡ 1 (mod 32): conflict-free
        float v[65];
        #pragma unroll
        for (int i = 0; i < 65; ++i) v[i] = rx[i];

        float grcp[8], mean[8];
#define GROUP_STATS(G, A, B, RSZ)                                       \
        {                                                               \
            float mm = v[A], s = 0.f;                                   \
            _Pragma("unroll")                                           \
            for (int i = A; i < B; ++i) { s += v[i]; mm = fmaxf(mm, v[i]); } \
            float e = 0.f;                                              \
            _Pragma("unroll")                                           \
            for (int i = A; i < B; ++i) { v[i] = __expf(v[i] - mm); e += v[i]; } \
            grcp[G] = 1.0f / e; mean[G] = s * (RSZ);                    \
        }
        GROUP_STATS(0,  0,  7, 1.0f/7.0f)
        GROUP_STATS(1,  7, 30, 1.0f/23.0f)
        GROUP_STATS(2, 30, 48, 1.0f/18.0f)
        GROUP_STATS(3, 48, 53, 1.0f/5.0f)
        GROUP_STATS(4, 53, 58, 1.0f/5.0f)
        GROUP_STATS(5, 58, 59, 1.0f)
        GROUP_STATS(6, 59, 62, 1.0f/3.0f)
        GROUP_STATS(7, 62, 65, 1.0f/3.0f)
#undef GROUP_STATS

        // level-2 softmaxes + top softmax
        {
            float mx0 = fmaxf(fmaxf(mean[0], mean[1]), fmaxf(mean[2], mean[3]));
            float e0 = __expf(mean[0]-mx0), e1 = __expf(mean[1]-mx0);
            float e2 = __expf(mean[2]-mx0), e3 = __expf(mean[3]-mx0);
            float r0 = 1.0f / (e0 + e1 + e2 + e3);
            pl2[0] = e0*r0; pl2[1] = e1*r0; pl2[2] = e2*r0; pl2[3] = e3*r0;

            float mx1 = fmaxf(fmaxf(mean[4], mean[5]), fmaxf(mean[6], mean[7]));
            float f0 = __expf(mean[4]-mx1), f1 = __expf(mean[5]-mx1);
            float f2 = __expf(mean[6]-mx1), f3 = __expf(mean[7]-mx1);
            float r1 = 1.0f / (f0 + f1 + f2 + f3);
            pl2[4] = f0*r1; pl2[5] = f1*r1; pl2[6] = f2*r1; pl2[7] = f3*r1;

            float m0 = (mean[0]*7.f + mean[1]*23.f + mean[2]*18.f + mean[3]*5.f) * (1.0f/53.0f);
            float m1 = (mean[4]*5.f + mean[5]*1.f + mean[6]*3.f + mean[7]*3.f) * (1.0f/12.0f);
            float mxt = fmaxf(m0, m1);
            float t0 = __expf(m0 - mxt), t1 = __expf(m1 - mxt);
            float rt = 1.0f / (t0 + t1);
            pt0 = t0 * rt; pt1 = t1 * rt;
        }

        // path scale ks = grcp*pl2*pt; inv = 1/(pl2*pt) for later leaf recovery
        float ks[8];
        #pragma unroll
        for (int g = 0; g < 8; ++g) {
            float pp = pl2[g] * (g < 4 ? pt0 : pt1);
            ks[g] = grcp[g] * pp;
            inv[g] = 1.0f / pp;
        }

        // path probs in place (own row only)
#define PATH_WRITE(G, A, B)                                   \
        _Pragma("unroll")                                     \
        for (int i = A; i < B; ++i) rx[i] = v[i] * ks[G];
        PATH_WRITE(0,  0,  7)  PATH_WRITE(1,  7, 30)
        PATH_WRITE(2, 30, 48)  PATH_WRITE(3, 48, 53)
        PATH_WRITE(4, 53, 58)  PATH_WRITE(5, 58, 59)
        PATH_WRITE(6, 59, 62)  PATH_WRITE(7, 62, 65)
#undef PATH_WRITE
    }   // v[], grcp, mean, ks all dead here
    __syncthreads();

    // ---- Phase C: stream path probs out, 2080 float4 (read-only on buf) ----
    {
        float4* op4 = reinterpret_cast<float4*>(out_path + row0 * 65);
        const float4* b4 = reinterpret_cast<const float4*>(buf);
        #pragma unroll
        for (int k = 0; k < 17; ++k) {
            int idx = tid + k * NT;
            if (idx < 2080) __stcs(&op4[idx], b4[idx]);
        }
    }

    // ---- Phase C2: recover leaf probs = path * inv[g] (read-only on buf) ----
    float v[65];
    {
        const float* rx = buf + tid * 65;
#define LEAF_RECOVER(G, A, B)                                 \
        {                                                     \
            float iv = inv[G];                                \
            _Pragma("unroll")                                 \
            for (int i = A; i < B; ++i) v[i] = rx[i] * iv;    \
        }
        LEAF_RECOVER(0,  0,  7)  LEAF_RECOVER(1,  7, 30)
        LEAF_RECOVER(2, 30, 48)  LEAF_RECOVER(3, 48, 53)
        LEAF_RECOVER(4, 53, 58)  LEAF_RECOVER(5, 58, 59)
        LEAF_RECOVER(6, 59, 62)  LEAF_RECOVER(7, 62, 65)
#undef LEAF_RECOVER
    }
    __syncthreads();   // all reads of path layout done before node-layout overwrite

    // ---- Phase D: write node rows [128][76] in place ----
    {
        float* rn = buf + tid * 76;
        #pragma unroll
        for (int i = 0; i < 65; ++i) rn[i] = v[i];
        #pragma unroll
        for (int g = 0; g < 8; ++g) rn[65 + g] = pl2[g];
        rn[73] = pt0;
        rn[74] = pt1;
        rn[75] = 1.0f;
    }
    __syncthreads();

    // ---- Phase E: stream node_probs out, 128*76 = 2432 float4 exact ----
    {
        float4* on4 = reinterpret_cast<float4*>(out_node + row0 * 76);
        const float4* b4 = reinterpret_cast<const float4*>(buf);
        #pragma unroll
        for (int k = 0; k < 19; ++k) {
            int idx = tid + k * NT;
            __stcs(&on4[idx], b4[idx]);
        }
    }
}

extern "C" void kernel_launch(void* const* d_in, const int* in_sizes, int n_in,
                              void* d_out, int out_size)
{
    const float* x = (const float*)d_in[0];
    const long long N = (long long)in_sizes[0] / 65;   // 524288
    float* out_path = (float*)d_out;
    float* out_node = out_path + N * 65;

    const int blocks = (int)(N / ROWS);                // 4096
    molemap_kernel<<<blocks, NT>>>(x, out_path, out_node);
}

// round 9
// speedup vs baseline: 1.4086x; 1.0020x over previous
#include <cuda_runtime.h>
#include <cuda_bf16.h>

// Thread-per-row hierarchical softmax. 5 blocks/SM (smem = one 38912B buffer,
// regs <= 102 via launch_bounds); per-row scalars live in registers.
// Plain LDG/STG (no .cs hints — measured faster on this access pattern).
// Fused output layout (flat): [ leaf_path_probs (N*65) | node_probs (N*76) ]

#define NT   128
#define ROWS 128

__global__ __launch_bounds__(NT, 5)
void molemap_kernel(const float* __restrict__ x,
                    float* __restrict__ out_path,
                    float* __restrict__ out_node)
{
    // ONLY smem: reused buffer. input rows -> path probs (stride 65) -> node rows (stride 76)
    __shared__ __align__(16) float buf[ROWS * 76];   // 38912 B

    const int tid = threadIdx.x;
    const long long row0 = (long long)blockIdx.x * ROWS;

    // ---- Phase A: coalesced vectorized load, 128*65 = 2080 float4 ----
    {
        const float4* in4 = reinterpret_cast<const float4*>(x + row0 * 65);
        float4* b4 = reinterpret_cast<float4*>(buf);
        #pragma unroll
        for (int k = 0; k < 17; ++k) {
            int idx = tid + k * NT;
            if (idx < 2080) b4[idx] = in4[idx];
        }
    }
    __syncthreads();

    // Per-row scalars kept in REGISTERS across streaming phases (tid-private).
    float pl2[8], pt0, pt1, inv[8];

    // ---- Phase B: thread-per-row compute; path probs written in place ----
    {
        float* rx = buf + tid * 65;   // stride 65 ≡ 1 (mod 32): conflict-free
        float v[65];
        #pragma unroll
        for (int i = 0; i < 65; ++i) v[i] = rx[i];

        float grcp[8], mean[8];
#define GROUP_STATS(G, A, B, RSZ)                                       \
        {                                                               \
            float mm = v[A], s = 0.f;                                   \
            _Pragma("unroll")                                           \
            for (int i = A; i < B; ++i) { s += v[i]; mm = fmaxf(mm, v[i]); } \
            float e = 0.f;                                              \
            _Pragma("unroll")                                           \
            for (int i = A; i < B; ++i) { v[i] = __expf(v[i] - mm); e += v[i]; } \
            grcp[G] = 1.0f / e; mean[G] = s * (RSZ);                    \
        }
        GROUP_STATS(0,  0,  7, 1.0f/7.0f)
        GROUP_STATS(1,  7, 30, 1.0f/23.0f)
        GROUP_STATS(2, 30, 48, 1.0f/18.0f)
        GROUP_STATS(3, 48, 53, 1.0f/5.0f)
        GROUP_STATS(4, 53, 58, 1.0f/5.0f)
        GROUP_STATS(5, 58, 59, 1.0f)
        GROUP_STATS(6, 59, 62, 1.0f/3.0f)
        GROUP_STATS(7, 62, 65, 1.0f/3.0f)
#undef GROUP_STATS

        // level-2 softmaxes + top softmax
        {
            float mx0 = fmaxf(fmaxf(mean[0], mean[1]), fmaxf(mean[2], mean[3]));
            float e0 = __expf(mean[0]-mx0), e1 = __expf(mean[1]-mx0);
            float e2 = __expf(mean[2]-mx0), e3 = __expf(mean[3]-mx0);
            float r0 = 1.0f / (e0 + e1 + e2 + e3);
            pl2[0] = e0*r0; pl2[1] = e1*r0; pl2[2] = e2*r0; pl2[3] = e3*r0;

            float mx1 = fmaxf(fmaxf(mean[4], mean[5]), fmaxf(mean[6], mean[7]));
            float f0 = __expf(mean[4]-mx1), f1 = __expf(mean[5]-mx1);
            float f2 = __expf(mean[6]-mx1), f3 = __expf(mean[7]-mx1);
            float r1 = 1.0f / (f0 + f1 + f2 + f3);
            pl2[4] = f0*r1; pl2[5] = f1*r1; pl2[6] = f2*r1; pl2[7] = f3*r1;

            float m0 = (mean[0]*7.f + mean[1]*23.f + mean[2]*18.f + mean[3]*5.f) * (1.0f/53.0f);
            float m1 = (mean[4]*5.f + mean[5]*1.f + mean[6]*3.f + mean[7]*3.f) * (1.0f/12.0f);
            float mxt = fmaxf(m0, m1);
            float t0 = __expf(m0 - mxt), t1 = __expf(m1 - mxt);
            float rt = 1.0f / (t0 + t1);
            pt0 = t0 * rt; pt1 = t1 * rt;
        }

        // path scale ks = grcp*pl2*pt; inv = 1/(pl2*pt) for later leaf recovery
        float ks[8];
        #pragma unroll
        for (int g = 0; g < 8; ++g) {
            float pp = pl2[g] * (g < 4 ? pt0 : pt1);
            ks[g] = grcp[g] * pp;
            inv[g] = 1.0f / pp;
        }

        // path probs in place (own row only)
#define PATH_WRITE(G, A, B)                                   \
        _Pragma("unroll")                                     \
        for (int i = A; i < B; ++i) rx[i] = v[i] * ks[G];
        PATH_WRITE(0,  0,  7)  PATH_WRITE(1,  7, 30)
        PATH_WRITE(2, 30, 48)  PATH_WRITE(3, 48, 53)
        PATH_WRITE(4, 53, 58)  PATH_WRITE(5, 58, 59)
        PATH_WRITE(6, 59, 62)  PATH_WRITE(7, 62, 65)
#undef PATH_WRITE
    }   // v[], grcp, mean, ks all dead here
    __syncthreads();

    // ---- Phase C: stream path probs out, 2080 float4 (read-only on buf) ----
    {
        float4* op4 = reinterpret_cast<float4*>(out_path + row0 * 65);
        const float4* b4 = reinterpret_cast<const float4*>(buf);
        #pragma unroll
        for (int k = 0; k < 17; ++k) {
            int idx = tid + k * NT;
            if (idx < 2080) op4[idx] = b4[idx];
        }
    }

    // ---- Phase C2: recover leaf probs = path * inv[g] (read-only on buf) ----
    float v[65];
    {
        const float* rx = buf + tid * 65;
#define LEAF_RECOVER(G, A, B)                                 \
        {                                                     \
            float iv = inv[G];                                \
            _Pragma("unroll")                                 \
            for (int i = A; i < B; ++i) v[i] = rx[i] * iv;    \
        }
        LEAF_RECOVER(0,  0,  7)  LEAF_RECOVER(1,  7, 30)
        LEAF_RECOVER(2, 30, 48)  LEAF_RECOVER(3, 48, 53)
        LEAF_RECOVER(4, 53, 58)  LEAF_RECOVER(5, 58, 59)
        LEAF_RECOVER(6, 59, 62)  LEAF_RECOVER(7, 62, 65)
#undef LEAF_RECOVER
    }
    __syncthreads();   // all reads of path layout done before node-layout overwrite

    // ---- Phase D: write node rows [128][76] in place ----
    {
        float* rn = buf + tid * 76;
        #pragma unroll
        for (int i = 0; i < 65; ++i) rn[i] = v[i];
        #pragma unroll
        for (int g = 0; g < 8; ++g) rn[65 + g] = pl2[g];
        rn[73] = pt0;
        rn[74] = pt1;
        rn[75] = 1.0f;
    }
    __syncthreads();

    // ---- Phase E: stream node_probs out, 128*76 = 2432 float4 exact ----
    {
        float4* on4 = reinterpret_cast<float4*>(out_node + row0 * 76);
        const float4* b4 = reinterpret_cast<const float4*>(buf);
        #pragma unroll
        for (int k = 0; k < 19; ++k) {
            int idx = tid + k * NT;
            on4[idx] = b4[idx];
        }
    }
}

extern "C" void kernel_launch(void* const* d_in, const int* in_sizes, int n_in,
                              void* d_out, int out_size)
{
    const float* x = (const float*)d_in[0];
    const long long N = (long long)in_sizes[0] / 65;   // 524288
    float* out_path = (float*)d_out;
    float* out_node = out_path + N * 65;

    const int blocks = (int)(N / ROWS);                // 4096
    molemap_kernel<<<blocks, NT>>>(x, out_path, out_node);
}